// round 1
// baseline (speedup 1.0000x reference)
#include <cuda_runtime.h>
#include <math.h>

#define BMAX   4096
#define NCHUNK 8
#define BM 128
#define BN 128
#define BK 16

// ---------------- scratch (device globals, no allocation) ----------------
__device__ float g_sq[BMAX];
__device__ float g_posV[NCHUNK][BMAX];
__device__ int   g_posI[NCHUNK][BMAX];
__device__ float g_negV[NCHUNK][BMAX];
__device__ int   g_negI[NCHUNK][BMAX];
__device__ int   g_hardPos[BMAX];
__device__ int   g_hardNeg[BMAX];
__device__ int   g_valid[BMAX];
__device__ float g_loss[BMAX];

// ---------------- kernel 1: row sum of squares ----------------
__global__ void sqKernel(const float* __restrict__ emb, int D) {
    int i = blockIdx.x;
    const float4* row = reinterpret_cast<const float4*>(emb + (size_t)i * D);
    float s = 0.f;
    for (int k = threadIdx.x; k < D / 4; k += blockDim.x) {
        float4 v = row[k];
        s += v.x * v.x + v.y * v.y + v.z * v.z + v.w * v.w;
    }
    // warp + smem reduce (256 threads = 8 warps)
    for (int off = 16; off > 0; off >>= 1)
        s += __shfl_down_sync(0xFFFFFFFFu, s, off);
    __shared__ float ws[8];
    if ((threadIdx.x & 31) == 0) ws[threadIdx.x >> 5] = s;
    __syncthreads();
    if (threadIdx.x == 0) {
        float t = 0.f;
        for (int w = 0; w < 8; w++) t += ws[w];
        g_sq[i] = t;
    }
}

// ---------------- kernel 2: fused SGEMM + hard pos/neg selection ----------------
__global__ __launch_bounds__(256) void distKernel(
    const float* __restrict__ emb, const int* __restrict__ labels, int B, int D)
{
    __shared__ float As[BK][BM];   // As[k][m]
    __shared__ float Bs[BK][BN];   // Bs[k][n]

    const int tid   = threadIdx.x;
    const int tx    = tid & 15;        // column group 0..15
    const int ty    = tid >> 4;        // row group 0..15
    const int iBase = blockIdx.x * BM;
    const int chunk = blockIdx.y;
    const int jChunk = B / NCHUNK;
    const int jStart = chunk * jChunk;
    const int jEnd   = jStart + jChunk;

    // per-thread selection state for my 8 rows
    float bpV[8], bnV[8];
    int   bpI[8], bnI[8];
    int   myLab[8];
    float mySq[8];
#pragma unroll
    for (int r = 0; r < 8; r++) {
        bpV[r] = -1.f; bpI[r] = 0;
        bnV[r] = 3.4e38f; bnI[r] = 0;
        int i = iBase + ty * 8 + r;
        myLab[r] = labels[i];
        mySq[r]  = g_sq[i];
    }

    for (int j0 = jStart; j0 < jEnd; j0 += BN) {
        float acc[8][8];
#pragma unroll
        for (int r = 0; r < 8; r++)
#pragma unroll
            for (int c = 0; c < 8; c++) acc[r][c] = 0.f;

        for (int k0 = 0; k0 < D; k0 += BK) {
            // Load A tile (128 rows x 16 k) and B tile, transposed into smem.
            // 512 float4 per tile; 256 threads -> 2 each.
#pragma unroll
            for (int t = 0; t < 2; t++) {
                int f   = tid + t * 256;        // 0..511
                int row = f >> 2;               // 0..127
                int kg  = (f & 3) * 4;          // 0,4,8,12
                float4 a = *reinterpret_cast<const float4*>(
                    &emb[(size_t)(iBase + row) * D + k0 + kg]);
                As[kg + 0][row] = a.x; As[kg + 1][row] = a.y;
                As[kg + 2][row] = a.z; As[kg + 3][row] = a.w;
                float4 b = *reinterpret_cast<const float4*>(
                    &emb[(size_t)(j0 + row) * D + k0 + kg]);
                Bs[kg + 0][row] = b.x; Bs[kg + 1][row] = b.y;
                Bs[kg + 2][row] = b.z; Bs[kg + 3][row] = b.w;
            }
            __syncthreads();

#pragma unroll
            for (int kk = 0; kk < BK; kk++) {
                float4 a0 = *reinterpret_cast<const float4*>(&As[kk][ty * 8]);
                float4 a1 = *reinterpret_cast<const float4*>(&As[kk][ty * 8 + 4]);
                float4 b0 = *reinterpret_cast<const float4*>(&Bs[kk][tx * 8]);
                float4 b1 = *reinterpret_cast<const float4*>(&Bs[kk][tx * 8 + 4]);
                float av[8] = {a0.x, a0.y, a0.z, a0.w, a1.x, a1.y, a1.z, a1.w};
                float bv[8] = {b0.x, b0.y, b0.z, b0.w, b1.x, b1.y, b1.z, b1.w};
#pragma unroll
                for (int r = 0; r < 8; r++)
#pragma unroll
                    for (int c = 0; c < 8; c++)
                        acc[r][c] = fmaf(av[r], bv[c], acc[r][c]);
            }
            __syncthreads();
        }

        // Selection update for this 128x128 tile of d^2.
#pragma unroll
        for (int c = 0; c < 8; c++) {
            int j = j0 + tx * 8 + c;
            int   labj = __ldg(&labels[j]);
            float sqj  = g_sq[j];
#pragma unroll
            for (int r = 0; r < 8; r++) {
                int i = iBase + ty * 8 + r;
                float d2 = fmaxf(mySq[r] + sqj - 2.f * acc[r][c], 0.f);
                if (labj == myLab[r]) {
                    if (i != j) {
                        if (d2 > bpV[r] || (d2 == bpV[r] && j < bpI[r])) {
                            bpV[r] = d2; bpI[r] = j;
                        }
                    }
                } else {
                    if (d2 < bnV[r] || (d2 == bnV[r] && j < bnI[r])) {
                        bnV[r] = d2; bnI[r] = j;
                    }
                }
            }
        }
    }

    // Reduce across the 16 column-threads per row (lanes [0..15] / [16..31]).
#pragma unroll
    for (int r = 0; r < 8; r++) {
#pragma unroll
        for (int off = 8; off >= 1; off >>= 1) {
            float pv = __shfl_down_sync(0xFFFFFFFFu, bpV[r], off, 16);
            int   pi = __shfl_down_sync(0xFFFFFFFFu, bpI[r], off, 16);
            if (pv > bpV[r] || (pv == bpV[r] && pi < bpI[r])) { bpV[r] = pv; bpI[r] = pi; }
            float nv = __shfl_down_sync(0xFFFFFFFFu, bnV[r], off, 16);
            int   ni = __shfl_down_sync(0xFFFFFFFFu, bnI[r], off, 16);
            if (nv < bnV[r] || (nv == bnV[r] && ni < bnI[r])) { bnV[r] = nv; bnI[r] = ni; }
        }
        if (tx == 0) {
            int i = iBase + ty * 8 + r;
            g_posV[chunk][i] = bpV[r];
            g_posI[chunk][i] = bpI[r];
            g_negV[chunk][i] = bnV[r];
            g_negI[chunk][i] = bnI[r];
        }
    }
}

// ---------------- kernel 3: merge chunk partials ----------------
__global__ void mergeKernel(int B) {
    int i = blockIdx.x * blockDim.x + threadIdx.x;
    if (i >= B) return;
    float bv = -2.f; int bi = 0;
    float nv = 3.5e38f; int ni = 0;
    for (int c = 0; c < NCHUNK; c++) {
        float pv = g_posV[c][i]; int pi = g_posI[c][i];
        if (pv > bv || (pv == bv && pi < bi)) { bv = pv; bi = pi; }
        float qv = g_negV[c][i]; int qi = g_negI[c][i];
        if (qv < nv || (qv == nv && qi < ni)) { nv = qv; ni = qi; }
    }
    g_hardPos[i] = bi;
    g_hardNeg[i] = ni;
    g_valid[i]   = (bv > -0.5f) && (nv < 1e37f) ? 1 : 0;
}

// ---------------- kernel 4: exact dp/dn recompute + per-anchor loss ----------------
__global__ void lossKernel(const float* __restrict__ emb, int D) {
    int i  = blockIdx.x;
    int hp = g_hardPos[i];
    int hn = g_hardNeg[i];
    const float* a = emb + (size_t)i  * D;
    const float* p = emb + (size_t)hp * D;
    const float* n = emb + (size_t)hn * D;
    float sp = 0.f, sn = 0.f;
    for (int k = threadIdx.x * 4; k < D; k += blockDim.x * 4) {
        float4 va = *reinterpret_cast<const float4*>(a + k);
        float4 vp = *reinterpret_cast<const float4*>(p + k);
        float4 vn = *reinterpret_cast<const float4*>(n + k);
        float d;
        d = va.x - vp.x + 1e-6f; sp += d * d;
        d = va.y - vp.y + 1e-6f; sp += d * d;
        d = va.z - vp.z + 1e-6f; sp += d * d;
        d = va.w - vp.w + 1e-6f; sp += d * d;
        d = va.x - vn.x + 1e-6f; sn += d * d;
        d = va.y - vn.y + 1e-6f; sn += d * d;
        d = va.z - vn.z + 1e-6f; sn += d * d;
        d = va.w - vn.w + 1e-6f; sn += d * d;
    }
    for (int off = 16; off > 0; off >>= 1) {
        sp += __shfl_down_sync(0xFFFFFFFFu, sp, off);
        sn += __shfl_down_sync(0xFFFFFFFFu, sn, off);
    }
    __shared__ float wsp[4], wsn[4];
    int w = threadIdx.x >> 5;
    if ((threadIdx.x & 31) == 0) { wsp[w] = sp; wsn[w] = sn; }
    __syncthreads();
    if (threadIdx.x == 0) {
        float tp = wsp[0] + wsp[1] + wsp[2] + wsp[3];
        float tn = wsn[0] + wsn[1] + wsn[2] + wsn[3];
        float per = fmaxf(sqrtf(tp) - sqrtf(tn) + 0.3f, 0.f);
        g_loss[i] = g_valid[i] ? per : 0.f;
    }
}

// ---------------- kernel 5: deterministic final reduction ----------------
__global__ void finalKernel(float* __restrict__ out, int B) {
    __shared__ float ssum[1024];
    __shared__ int   scnt[1024];
    float s = 0.f; int c = 0;
    for (int i = threadIdx.x; i < B; i += 1024) {
        s += g_loss[i];
        c += g_valid[i];
    }
    ssum[threadIdx.x] = s;
    scnt[threadIdx.x] = c;
    __syncthreads();
    for (int off = 512; off > 0; off >>= 1) {
        if (threadIdx.x < off) {
            ssum[threadIdx.x] += ssum[threadIdx.x + off];
            scnt[threadIdx.x] += scnt[threadIdx.x + off];
        }
        __syncthreads();
    }
    if (threadIdx.x == 0)
        out[0] = (scnt[0] > 0) ? ssum[0] / (float)scnt[0] : 0.f;
}

// ---------------- launch ----------------
extern "C" void kernel_launch(void* const* d_in, const int* in_sizes, int n_in,
                              void* d_out, int out_size) {
    const float* emb    = (const float*)d_in[0];
    const int*   labels = (const int*)d_in[1];
    float*       out    = (float*)d_out;
    int B = in_sizes[1];
    int D = in_sizes[0] / B;

    sqKernel<<<B, 256>>>(emb, D);
    dim3 grid(B / BM, NCHUNK);
    distKernel<<<grid, 256>>>(emb, labels, B, D);
    mergeKernel<<<(B + 255) / 256, 256>>>(B);
    lossKernel<<<B, 128>>>(emb, D);
    finalKernel<<<1, 1024>>>(out, B);
}

// round 3
// speedup vs baseline: 9.8360x; 9.8360x over previous
#include <cuda_runtime.h>
#include <cuda_bf16.h>
#include <cstdint>
#include <math.h>

// ===================== constants =====================
#define BMAX   4096
#define DMAX   2048
#define BM 128
#define BN 128
#define TBK 64                      // bf16 K per chunk = 128 bytes/row
#define STAGES 3
#define A_BYTES (BM*TBK*2)          // 16384
#define B_BYTES (BN*TBK*2)          // 16384
#define STAGE_BYTES (A_BYTES+B_BYTES)   // 32768
#define SEL_OFF (STAGES*STAGE_BYTES)    // 98304
#define SMEM_TOTAL (SEL_OFF + 10240)    // 108544
#define NCHUNK (BMAX/BN)            // 32

// ===================== device scratch =====================
__device__ __nv_bfloat16 g_ebf[(size_t)BMAX * DMAX];
__device__ float g_sq[BMAX];
__device__ float g_posV[NCHUNK][BMAX];
__device__ int   g_posI[NCHUNK][BMAX];
__device__ float g_negV[NCHUNK][BMAX];
__device__ int   g_negI[NCHUNK][BMAX];
__device__ int   g_hardPos[BMAX];
__device__ int   g_hardNeg[BMAX];
__device__ int   g_valid[BMAX];
__device__ float g_loss[BMAX];

// ===================== helpers =====================
__device__ __forceinline__ uint32_t smem_u32(const void* p) {
    uint32_t a;
    asm("{ .reg .u64 t; cvta.to.shared.u64 t, %1; cvt.u32.u64 %0, t; }" : "=r"(a) : "l"(p));
    return a;
}
__device__ __forceinline__ void cpa16(uint32_t s, const void* g) {
    asm volatile("cp.async.cg.shared.global [%0], [%1], 16;" :: "r"(s), "l"(g));
}
#define CPA_COMMIT() asm volatile("cp.async.commit_group;" ::: "memory")
#define CPA_WAIT(N)  asm volatile("cp.async.wait_group %0;" :: "n"(N) : "memory")

__device__ __forceinline__ void ldsm4(uint32_t* r, uint32_t addr) {
    asm volatile("ldmatrix.sync.aligned.m8n8.x4.shared.b16 {%0,%1,%2,%3}, [%4];"
                 : "=r"(r[0]), "=r"(r[1]), "=r"(r[2]), "=r"(r[3]) : "r"(addr));
}
__device__ __forceinline__ void mma16816(float* c, const uint32_t* a, const uint32_t* b) {
    asm volatile(
        "mma.sync.aligned.m16n8k16.row.col.f32.bf16.bf16.f32 "
        "{%0,%1,%2,%3}, {%4,%5,%6,%7}, {%8,%9}, {%0,%1,%2,%3};"
        : "+f"(c[0]), "+f"(c[1]), "+f"(c[2]), "+f"(c[3])
        : "r"(a[0]), "r"(a[1]), "r"(a[2]), "r"(a[3]), "r"(b[0]), "r"(b[1]));
}

__device__ __forceinline__ void selMax(float& v, int& i, float nv, int ni) {
    if (nv > v || (nv == v && ni < i)) { v = nv; i = ni; }
}
__device__ __forceinline__ void selMin(float& v, int& i, float nv, int ni) {
    if (nv < v || (nv == v && ni < i)) { v = nv; i = ni; }
}

// ===================== kernel 1: fp32 -> bf16 + row sumsq =====================
__global__ void convKernel(const float* __restrict__ emb, int D) {
    int i = blockIdx.x;
    const float4* row = reinterpret_cast<const float4*>(emb + (size_t)i * D);
    __nv_bfloat162* orow = reinterpret_cast<__nv_bfloat162*>(g_ebf + (size_t)i * D);
    float s = 0.f;
    for (int k = threadIdx.x; k < D / 4; k += blockDim.x) {
        float4 v = row[k];
        s += v.x * v.x + v.y * v.y + v.z * v.z + v.w * v.w;
        __nv_bfloat162 h0, h1;
        h0.x = __float2bfloat16(v.x); h0.y = __float2bfloat16(v.y);
        h1.x = __float2bfloat16(v.z); h1.y = __float2bfloat16(v.w);
        orow[2 * k] = h0; orow[2 * k + 1] = h1;
    }
    for (int off = 16; off > 0; off >>= 1)
        s += __shfl_down_sync(0xFFFFFFFFu, s, off);
    __shared__ float ws[8];
    if ((threadIdx.x & 31) == 0) ws[threadIdx.x >> 5] = s;
    __syncthreads();
    if (threadIdx.x == 0) {
        float t = 0.f;
        for (int w = 0; w < (int)(blockDim.x >> 5); w++) t += ws[w];
        g_sq[i] = t;
    }
}

// ===================== kernel 2: bf16 HMMA GEMM + selection =====================
__device__ __forceinline__ void load_chunk(int tid, uint32_t sbase, int s,
                                           int iBase, int jBase, int c, int D) {
    uint32_t sA = sbase + s * STAGE_BYTES;
    uint32_t sB = sA + A_BYTES;
    int k0 = c * TBK;
    const char* gA = (const char*)(g_ebf + (size_t)iBase * D + k0);
    const char* gB = (const char*)(g_ebf + (size_t)jBase * D + k0);
#pragma unroll
    for (int t = 0; t < 4; t++) {
        int f = tid + t * 256;
        int row = f >> 3, c16 = f & 7;
        int colb = c16 * 16;
        uint32_t off = (uint32_t)(row * 128 + (colb ^ ((row & 7) << 4)));
        cpa16(sA + off, gA + (size_t)row * (size_t)(D * 2) + colb);
    }
#pragma unroll
    for (int t = 0; t < 4; t++) {
        int f = tid + t * 256;
        int row = f >> 3, c16 = f & 7;
        int colb = c16 * 16;
        uint32_t off = (uint32_t)(row * 128 + (colb ^ ((row & 7) << 4)));
        cpa16(sB + off, gB + (size_t)row * (size_t)(D * 2) + colb);
    }
    CPA_COMMIT();
}

__global__ __launch_bounds__(256, 2) void distKernel(const int* __restrict__ labels,
                                                     int B, int D) {
    extern __shared__ char sm[];
    uint32_t sbase = smem_u32(sm);

    const int tid  = threadIdx.x;
    const int wid  = tid >> 5;
    const int lane = tid & 31;
    const int warpM = wid & 1;       // 0..1 (64 rows each)
    const int warpN = wid >> 1;      // 0..3 (32 cols each)
    const int iBase = blockIdx.x * BM;
    const int jBase = blockIdx.y * BN;

    float* sPosV = (float*)(sm + SEL_OFF);
    int*   sPosI = (int*)  (sm + SEL_OFF + 2048);
    float* sNegV = (float*)(sm + SEL_OFF + 4096);
    int*   sNegI = (int*)  (sm + SEL_OFF + 6144);
    int*   sLabJ = (int*)  (sm + SEL_OFF + 8192);
    float* sSqJ  = (float*)(sm + SEL_OFF + 8704);
    int*   sLabI = (int*)  (sm + SEL_OFF + 9216);
    float* sSqI  = (float*)(sm + SEL_OFF + 9728);

    // preload labels/sq for this CTA's rows and cols
    if (tid < 128) {
        sLabJ[tid] = labels[jBase + tid];
        sSqJ[tid]  = g_sq[jBase + tid];
        sLabI[tid] = labels[iBase + tid];
        sSqI[tid]  = g_sq[iBase + tid];
    }

    // ldmatrix per-lane invariants
    const int rowA_l = (lane & 7) + ((lane >> 3) & 1) * 8;   // 0..15
    const int colA_b = (lane >> 4) * 16;
    const int rowB_l = (lane & 7) + (lane >> 4) * 8;         // 0..15
    const int colB_b = ((lane >> 3) & 1) * 16;

    int aRow[4], bRow[2];
#pragma unroll
    for (int mf = 0; mf < 4; mf++) aRow[mf] = warpM * 64 + mf * 16 + rowA_l;
#pragma unroll
    for (int nf = 0; nf < 2; nf++) bRow[nf] = warpN * 32 + nf * 16 + rowB_l;

    float acc[4][4][4];
#pragma unroll
    for (int a = 0; a < 4; a++)
#pragma unroll
        for (int b = 0; b < 4; b++)
#pragma unroll
            for (int c = 0; c < 4; c++) acc[a][b][c] = 0.f;

    const int nch = D / TBK;     // 32

    // prologue: stages 0,1
    load_chunk(tid, sbase, 0, iBase, jBase, 0, D);
    load_chunk(tid, sbase, 1, iBase, jBase, 1, D);

    for (int c = 0; c < nch; c++) {
        if (c == nch - 1) { CPA_WAIT(0); } else { CPA_WAIT(1); }
        __syncthreads();
        if (c + 2 < nch)
            load_chunk(tid, sbase, (c + 2) % STAGES, iBase, jBase, c + 2, D);

        uint32_t sA = sbase + (c % STAGES) * STAGE_BYTES;
        uint32_t sB = sA + A_BYTES;
#pragma unroll
        for (int ks = 0; ks < TBK / 16; ks++) {
            uint32_t aF[16], bF[8];
#pragma unroll
            for (int mf = 0; mf < 4; mf++) {
                int r = aRow[mf];
                uint32_t addr = sA + r * 128 + ((ks * 32 + colA_b) ^ ((r & 7) << 4));
                ldsm4(aF + mf * 4, addr);
            }
#pragma unroll
            for (int nf = 0; nf < 2; nf++) {
                int r = bRow[nf];
                uint32_t addr = sB + r * 128 + ((ks * 32 + colB_b) ^ ((r & 7) << 4));
                ldsm4(bF + nf * 4, addr);
            }
#pragma unroll
            for (int mf = 0; mf < 4; mf++)
#pragma unroll
                for (int n8 = 0; n8 < 4; n8++)
                    mma16816(acc[mf][n8], aF + mf * 4, bF + n8 * 2);
        }
    }
    __syncthreads();

    // ---- epilogue: d^2 + hard pos/neg selection ----
    const int g = lane >> 2;     // 0..7
    const int q = lane & 3;      // 0..3

    int   jLab[8];
    float jSq[8];
#pragma unroll
    for (int n8 = 0; n8 < 4; n8++)
#pragma unroll
        for (int cc = 0; cc < 2; cc++) {
            int jj = warpN * 32 + n8 * 8 + q * 2 + cc;
            jLab[n8 * 2 + cc] = sLabJ[jj];
            jSq[n8 * 2 + cc]  = sSqJ[jj];
        }

#pragma unroll
    for (int mf = 0; mf < 4; mf++) {
#pragma unroll
        for (int h = 0; h < 2; h++) {
            int rl   = warpM * 64 + mf * 16 + h * 8 + g;
            int iRow = iBase + rl;
            float sqi = sSqI[rl];
            int   lab = sLabI[rl];
            float bpV = -1.f, bnV = 3.4e38f;
            int   bpI = 1 << 30, bnI = 1 << 30;
#pragma unroll
            for (int n8 = 0; n8 < 4; n8++)
#pragma unroll
                for (int cc = 0; cc < 2; cc++) {
                    int j = jBase + warpN * 32 + n8 * 8 + q * 2 + cc;
                    float dot = acc[mf][n8][h * 2 + cc];
                    float d2 = fmaxf(sqi + jSq[n8 * 2 + cc] - 2.f * dot, 0.f);
                    if (jLab[n8 * 2 + cc] == lab) {
                        if (j != iRow) selMax(bpV, bpI, d2, j);
                    } else {
                        selMin(bnV, bnI, d2, j);
                    }
                }
            // quad reduce (lanes sharing g)
#pragma unroll
            for (int off = 1; off <= 2; off <<= 1) {
                float pv = __shfl_xor_sync(0xFFFFFFFFu, bpV, off);
                int   pi = __shfl_xor_sync(0xFFFFFFFFu, bpI, off);
                selMax(bpV, bpI, pv, pi);
                float nv = __shfl_xor_sync(0xFFFFFFFFu, bnV, off);
                int   ni = __shfl_xor_sync(0xFFFFFFFFu, bnI, off);
                selMin(bnV, bnI, nv, ni);
            }
            if (q == 0) {
                sPosV[rl * 4 + warpN] = bpV;
                sPosI[rl * 4 + warpN] = bpI;
                sNegV[rl * 4 + warpN] = bnV;
                sNegI[rl * 4 + warpN] = bnI;
            }
        }
    }
    __syncthreads();

    if (tid < 128) {
        float bpV = -2.f, bnV = 3.5e38f;
        int bpI = 1 << 30, bnI = 1 << 30;
#pragma unroll
        for (int wn = 0; wn < 4; wn++) {
            selMax(bpV, bpI, sPosV[tid * 4 + wn], sPosI[tid * 4 + wn]);
            selMin(bnV, bnI, sNegV[tid * 4 + wn], sNegI[tid * 4 + wn]);
        }
        int iRow = iBase + tid;
        g_posV[blockIdx.y][iRow] = bpV;
        g_posI[blockIdx.y][iRow] = bpI;
        g_negV[blockIdx.y][iRow] = bnV;
        g_negI[blockIdx.y][iRow] = bnI;
    }
}

// ===================== kernel 3: merge chunk partials =====================
__global__ void mergeKernel(int B) {
    int i = blockIdx.x * blockDim.x + threadIdx.x;
    if (i >= B) return;
    float bv = -2.f; int bi = 1 << 30;
    float nv = 3.5e38f; int ni = 1 << 30;
    for (int c = 0; c < NCHUNK; c++) {
        selMax(bv, bi, g_posV[c][i], g_posI[c][i]);
        selMin(nv, ni, g_negV[c][i], g_negI[c][i]);
    }
    g_hardPos[i] = (bi < BMAX) ? bi : 0;
    g_hardNeg[i] = (ni < BMAX) ? ni : 0;
    g_valid[i]   = (bv > -0.5f) && (nv < 1e37f) ? 1 : 0;
}

// ===================== kernel 4: exact dp/dn recompute =====================
__global__ void lossKernel(const float* __restrict__ emb, int D) {
    int i  = blockIdx.x;
    int hp = g_hardPos[i];
    int hn = g_hardNeg[i];
    const float* a = emb + (size_t)i  * D;
    const float* p = emb + (size_t)hp * D;
    const float* n = emb + (size_t)hn * D;
    float sp = 0.f, sn = 0.f;
    for (int k = threadIdx.x * 4; k < D; k += blockDim.x * 4) {
        float4 va = *reinterpret_cast<const float4*>(a + k);
        float4 vp = *reinterpret_cast<const float4*>(p + k);
        float4 vn = *reinterpret_cast<const float4*>(n + k);
        float d;
        d = va.x - vp.x + 1e-6f; sp += d * d;
        d = va.y - vp.y + 1e-6f; sp += d * d;
        d = va.z - vp.z + 1e-6f; sp += d * d;
        d = va.w - vp.w + 1e-6f; sp += d * d;
        d = va.x - vn.x + 1e-6f; sn += d * d;
        d = va.y - vn.y + 1e-6f; sn += d * d;
        d = va.z - vn.z + 1e-6f; sn += d * d;
        d = va.w - vn.w + 1e-6f; sn += d * d;
    }
    for (int off = 16; off > 0; off >>= 1) {
        sp += __shfl_down_sync(0xFFFFFFFFu, sp, off);
        sn += __shfl_down_sync(0xFFFFFFFFu, sn, off);
    }
    __shared__ float wsp[4], wsn[4];
    int w = threadIdx.x >> 5;
    if ((threadIdx.x & 31) == 0) { wsp[w] = sp; wsn[w] = sn; }
    __syncthreads();
    if (threadIdx.x == 0) {
        float tp = wsp[0] + wsp[1] + wsp[2] + wsp[3];
        float tn = wsn[0] + wsn[1] + wsn[2] + wsn[3];
        float per = fmaxf(sqrtf(tp) - sqrtf(tn) + 0.3f, 0.f);
        g_loss[i] = g_valid[i] ? per : 0.f;
    }
}

// ===================== kernel 5: final reduction =====================
__global__ void finalKernel(float* __restrict__ out, int B) {
    __shared__ float ssum[1024];
    __shared__ int   scnt[1024];
    float s = 0.f; int c = 0;
    for (int i = threadIdx.x; i < B; i += 1024) {
        s += g_loss[i];
        c += g_valid[i];
    }
    ssum[threadIdx.x] = s;
    scnt[threadIdx.x] = c;
    __syncthreads();
    for (int off = 512; off > 0; off >>= 1) {
        if (threadIdx.x < off) {
            ssum[threadIdx.x] += ssum[threadIdx.x + off];
            scnt[threadIdx.x] += scnt[threadIdx.x + off];
        }
        __syncthreads();
    }
    if (threadIdx.x == 0)
        out[0] = (scnt[0] > 0) ? ssum[0] / (float)scnt[0] : 0.f;
}

// ===================== launch =====================
extern "C" void kernel_launch(void* const* d_in, const int* in_sizes, int n_in,
                              void* d_out, int out_size) {
    const float* emb    = (const float*)d_in[0];
    const int*   labels = (const int*)d_in[1];
    float*       out    = (float*)d_out;
    int B = in_sizes[1];
    int D = in_sizes[0] / B;

    cudaFuncSetAttribute(distKernel, cudaFuncAttributeMaxDynamicSharedMemorySize, SMEM_TOTAL);

    convKernel<<<B, 256>>>(emb, D);
    dim3 grid(B / BM, B / BN);
    distKernel<<<grid, 256, SMEM_TOTAL>>>(labels, B, D);
    mergeKernel<<<(B + 255) / 256, 256>>>(B);
    lossKernel<<<B, 128>>>(emb, D);
    finalKernel<<<1, 1024>>>(out, B);
}

// round 4
// speedup vs baseline: 14.7752x; 1.5021x over previous
#include <cuda_runtime.h>
#include <cuda_bf16.h>
#include <cstdint>
#include <math.h>

// ===================== constants =====================
#define BMAX   4096
#define DMAX   2048
#define BM 128
#define BN 128
#define TBK 64                      // bf16 K per chunk = 128 bytes/row
#define STAGES 3
#define A_BYTES (BM*TBK*2)          // 16384
#define B_BYTES (BN*TBK*2)          // 16384
#define STAGE_BYTES (A_BYTES+B_BYTES)   // 32768
#define SEL_OFF (STAGES*STAGE_BYTES)    // 98304
#define SMEM_TOTAL (SEL_OFF + 14336)    // 112640
#define NCHUNK (BMAX/BN)            // 32

// ===================== device scratch =====================
__device__ __nv_bfloat16 g_ebf[(size_t)BMAX * DMAX];
__device__ float g_sq[BMAX];
__device__ float g_posV[NCHUNK][BMAX];
__device__ int   g_posI[NCHUNK][BMAX];
__device__ float g_negV[NCHUNK][BMAX];
__device__ int   g_negI[NCHUNK][BMAX];
__device__ int   g_hardPos[BMAX];
__device__ int   g_hardNeg[BMAX];
__device__ int   g_valid[BMAX];
__device__ float g_loss[BMAX];

// ===================== helpers =====================
__device__ __forceinline__ uint32_t smem_u32(const void* p) {
    uint32_t a;
    asm("{ .reg .u64 t; cvta.to.shared.u64 t, %1; cvt.u32.u64 %0, t; }" : "=r"(a) : "l"(p));
    return a;
}
__device__ __forceinline__ void cpa16(uint32_t s, const void* g) {
    asm volatile("cp.async.cg.shared.global [%0], [%1], 16;" :: "r"(s), "l"(g));
}
#define CPA_COMMIT() asm volatile("cp.async.commit_group;" ::: "memory")
#define CPA_WAIT(N)  asm volatile("cp.async.wait_group %0;" :: "n"(N) : "memory")

__device__ __forceinline__ void ldsm4(uint32_t* r, uint32_t addr) {
    asm volatile("ldmatrix.sync.aligned.m8n8.x4.shared.b16 {%0,%1,%2,%3}, [%4];"
                 : "=r"(r[0]), "=r"(r[1]), "=r"(r[2]), "=r"(r[3]) : "r"(addr));
}
__device__ __forceinline__ void mma16816(float* c, const uint32_t* a, const uint32_t* b) {
    asm volatile(
        "mma.sync.aligned.m16n8k16.row.col.f32.bf16.bf16.f32 "
        "{%0,%1,%2,%3}, {%4,%5,%6,%7}, {%8,%9}, {%0,%1,%2,%3};"
        : "+f"(c[0]), "+f"(c[1]), "+f"(c[2]), "+f"(c[3])
        : "r"(a[0]), "r"(a[1]), "r"(a[2]), "r"(a[3]), "r"(b[0]), "r"(b[1]));
}

__device__ __forceinline__ void selMax(float& v, int& i, float nv, int ni) {
    if (nv > v || (nv == v && ni < i)) { v = nv; i = ni; }
}
__device__ __forceinline__ void selMin(float& v, int& i, float nv, int ni) {
    if (nv < v || (nv == v && ni < i)) { v = nv; i = ni; }
}

// ===================== kernel 1: fp32 -> bf16 + row sumsq =====================
__global__ void convKernel(const float* __restrict__ emb, int D) {
    int i = blockIdx.x;
    const float4* row = reinterpret_cast<const float4*>(emb + (size_t)i * D);
    __nv_bfloat162* orow = reinterpret_cast<__nv_bfloat162*>(g_ebf + (size_t)i * D);
    float s = 0.f;
    for (int k = threadIdx.x; k < D / 4; k += blockDim.x) {
        float4 v = row[k];
        s += v.x * v.x + v.y * v.y + v.z * v.z + v.w * v.w;
        __nv_bfloat162 h0, h1;
        h0.x = __float2bfloat16(v.x); h0.y = __float2bfloat16(v.y);
        h1.x = __float2bfloat16(v.z); h1.y = __float2bfloat16(v.w);
        orow[2 * k] = h0; orow[2 * k + 1] = h1;
    }
    for (int off = 16; off > 0; off >>= 1)
        s += __shfl_down_sync(0xFFFFFFFFu, s, off);
    __shared__ float ws[8];
    if ((threadIdx.x & 31) == 0) ws[threadIdx.x >> 5] = s;
    __syncthreads();
    if (threadIdx.x == 0) {
        float t = 0.f;
        for (int w = 0; w < (int)(blockDim.x >> 5); w++) t += ws[w];
        g_sq[i] = t;
    }
}

// ===================== kernel 2: bf16 HMMA GEMM (upper triangle) + dual selection ==========
__device__ __forceinline__ void load_chunk(int tid, uint32_t sbase, int s,
                                           int iBase, int jBase, int c, int D) {
    uint32_t sA = sbase + s * STAGE_BYTES;
    uint32_t sB = sA + A_BYTES;
    int k0 = c * TBK;
    const char* gA = (const char*)(g_ebf + (size_t)iBase * D + k0);
    const char* gB = (const char*)(g_ebf + (size_t)jBase * D + k0);
#pragma unroll
    for (int t = 0; t < 4; t++) {
        int f = tid + t * 256;
        int row = f >> 3, c16 = f & 7;
        int colb = c16 * 16;
        uint32_t off = (uint32_t)(row * 128 + (colb ^ ((row & 7) << 4)));
        cpa16(sA + off, gA + (size_t)row * (size_t)(D * 2) + colb);
    }
#pragma unroll
    for (int t = 0; t < 4; t++) {
        int f = tid + t * 256;
        int row = f >> 3, c16 = f & 7;
        int colb = c16 * 16;
        uint32_t off = (uint32_t)(row * 128 + (colb ^ ((row & 7) << 4)));
        cpa16(sB + off, gB + (size_t)row * (size_t)(D * 2) + colb);
    }
    CPA_COMMIT();
}

__global__ __launch_bounds__(256, 2) void distKernel(const int* __restrict__ labels,
                                                     int B, int D) {
    extern __shared__ char sm[];
    uint32_t sbase = smem_u32(sm);

    const int tid  = threadIdx.x;
    const int wid  = tid >> 5;
    const int lane = tid & 31;
    const int warpM = wid & 1;       // 0..1 (64 rows each)
    const int warpN = wid >> 1;      // 0..3 (32 cols each)

    // decode upper-triangular tile (bi <= bj)
    const int nb = B / BM;           // 32
    int bi = 0, rem = blockIdx.x;
    while (rem >= nb - bi) { rem -= nb - bi; bi++; }
    const int bj = bi + rem;
    const int iBase = bi * BM;
    const int jBase = bj * BN;
    const bool diag = (bi == bj);

    float* sPosV = (float*)(sm + SEL_OFF);
    int*   sPosI = (int*)  (sm + SEL_OFF + 2048);
    float* sNegV = (float*)(sm + SEL_OFF + 4096);
    int*   sNegI = (int*)  (sm + SEL_OFF + 6144);
    int*   sLabJ = (int*)  (sm + SEL_OFF + 8192);
    float* sSqJ  = (float*)(sm + SEL_OFF + 8704);
    int*   sLabI = (int*)  (sm + SEL_OFF + 9216);
    float* sSqI  = (float*)(sm + SEL_OFF + 9728);
    float* sPosVc = (float*)(sm + SEL_OFF + 10240);
    int*   sPosIc = (int*)  (sm + SEL_OFF + 11264);
    float* sNegVc = (float*)(sm + SEL_OFF + 12288);
    int*   sNegIc = (int*)  (sm + SEL_OFF + 13312);

    if (tid < 128) {
        sLabJ[tid] = labels[jBase + tid];
        sSqJ[tid]  = g_sq[jBase + tid];
        sLabI[tid] = labels[iBase + tid];
        sSqI[tid]  = g_sq[iBase + tid];
    }

    // ldmatrix per-lane invariants
    const int rowA_l = (lane & 7) + ((lane >> 3) & 1) * 8;
    const int colA_b = (lane >> 4) * 16;
    const int rowB_l = (lane & 7) + (lane >> 4) * 8;
    const int colB_b = ((lane >> 3) & 1) * 16;

    int aRow[4], bRow[2];
#pragma unroll
    for (int mf = 0; mf < 4; mf++) aRow[mf] = warpM * 64 + mf * 16 + rowA_l;
#pragma unroll
    for (int nf = 0; nf < 2; nf++) bRow[nf] = warpN * 32 + nf * 16 + rowB_l;

    float acc[4][4][4];
#pragma unroll
    for (int a = 0; a < 4; a++)
#pragma unroll
        for (int b = 0; b < 4; b++)
#pragma unroll
            for (int c = 0; c < 4; c++) acc[a][b][c] = 0.f;

    const int nch = D / TBK;     // 32

    load_chunk(tid, sbase, 0, iBase, jBase, 0, D);
    load_chunk(tid, sbase, 1, iBase, jBase, 1, D);

    for (int c = 0; c < nch; c++) {
        if (c == nch - 1) { CPA_WAIT(0); } else { CPA_WAIT(1); }
        __syncthreads();
        if (c + 2 < nch)
            load_chunk(tid, sbase, (c + 2) % STAGES, iBase, jBase, c + 2, D);

        uint32_t sA = sbase + (c % STAGES) * STAGE_BYTES;
        uint32_t sB = sA + A_BYTES;
#pragma unroll
        for (int ks = 0; ks < TBK / 16; ks++) {
            uint32_t aF[16], bF[8];
#pragma unroll
            for (int mf = 0; mf < 4; mf++) {
                int r = aRow[mf];
                uint32_t addr = sA + r * 128 + ((ks * 32 + colA_b) ^ ((r & 7) << 4));
                ldsm4(aF + mf * 4, addr);
            }
#pragma unroll
            for (int nf = 0; nf < 2; nf++) {
                int r = bRow[nf];
                uint32_t addr = sB + r * 128 + ((ks * 32 + colB_b) ^ ((r & 7) << 4));
                ldsm4(bF + nf * 4, addr);
            }
#pragma unroll
            for (int mf = 0; mf < 4; mf++)
#pragma unroll
                for (int n8 = 0; n8 < 4; n8++)
                    mma16816(acc[mf][n8], aF + mf * 4, bF + n8 * 2);
        }
    }
    __syncthreads();

    // ---- epilogue: d^2 + dual hard pos/neg selection (row + column anchors) ----
    const int g = lane >> 2;     // 0..7
    const int q = lane & 3;      // 0..3

    int   jLab[8];
    float jSq[8];
    int   jIdx[8];
#pragma unroll
    for (int n8 = 0; n8 < 4; n8++)
#pragma unroll
        for (int cc = 0; cc < 2; cc++) {
            int jj = warpN * 32 + n8 * 8 + q * 2 + cc;
            jLab[n8 * 2 + cc] = sLabJ[jj];
            jSq[n8 * 2 + cc]  = sSqJ[jj];
            jIdx[n8 * 2 + cc] = jBase + jj;
        }

    // column-anchor accumulators (8 columns per thread)
    float cpV[8], cnV[8];
    int   cpI[8], cnI[8];
#pragma unroll
    for (int t = 0; t < 8; t++) {
        cpV[t] = -1.f; cpI[t] = 1 << 30;
        cnV[t] = 3.4e38f; cnI[t] = 1 << 30;
    }

#pragma unroll
    for (int mf = 0; mf < 4; mf++) {
#pragma unroll
        for (int h = 0; h < 2; h++) {
            int rl   = warpM * 64 + mf * 16 + h * 8 + g;
            int iRow = iBase + rl;
            float sqi = sSqI[rl];
            int   lab = sLabI[rl];
            float bpV = -1.f, bnV = 3.4e38f;
            int   bpI = 1 << 30, bnI = 1 << 30;
#pragma unroll
            for (int t = 0; t < 8; t++) {
                int n8 = t >> 1, cc = t & 1;
                int j = jIdx[t];
                float dot = acc[mf][n8][h * 2 + cc];
                float d2 = fmaxf(sqi + jSq[t] - 2.f * dot, 0.f);
                if (jLab[t] == lab) {
                    if (j != iRow) {
                        selMax(bpV, bpI, d2, j);
                        selMax(cpV[t], cpI[t], d2, iRow);
                    }
                } else {
                    selMin(bnV, bnI, d2, j);
                    selMin(cnV[t], cnI[t], d2, iRow);
                }
            }
            // row-anchor quad reduce (across q lanes)
#pragma unroll
            for (int off = 1; off <= 2; off <<= 1) {
                float pv = __shfl_xor_sync(0xFFFFFFFFu, bpV, off);
                int   pi = __shfl_xor_sync(0xFFFFFFFFu, bpI, off);
                selMax(bpV, bpI, pv, pi);
                float nv = __shfl_xor_sync(0xFFFFFFFFu, bnV, off);
                int   ni = __shfl_xor_sync(0xFFFFFFFFu, bnI, off);
                selMin(bnV, bnI, nv, ni);
            }
            if (q == 0) {
                sPosV[rl * 4 + warpN] = bpV;
                sPosI[rl * 4 + warpN] = bpI;
                sNegV[rl * 4 + warpN] = bnV;
                sNegI[rl * 4 + warpN] = bnI;
            }
        }
    }

    if (!diag) {
        // column-anchor reduce across g lanes (xor 4, 8, 16)
#pragma unroll
        for (int t = 0; t < 8; t++) {
#pragma unroll
            for (int off = 4; off <= 16; off <<= 1) {
                float pv = __shfl_xor_sync(0xFFFFFFFFu, cpV[t], off);
                int   pi = __shfl_xor_sync(0xFFFFFFFFu, cpI[t], off);
                selMax(cpV[t], cpI[t], pv, pi);
                float nv = __shfl_xor_sync(0xFFFFFFFFu, cnV[t], off);
                int   ni = __shfl_xor_sync(0xFFFFFFFFu, cnI[t], off);
                selMin(cnV[t], cnI[t], nv, ni);
            }
        }
        if (g == 0) {
#pragma unroll
            for (int t = 0; t < 8; t++) {
                int n8 = t >> 1, cc = t & 1;
                int jj = warpN * 32 + n8 * 8 + q * 2 + cc;
                sPosVc[jj * 2 + warpM] = cpV[t];
                sPosIc[jj * 2 + warpM] = cpI[t];
                sNegVc[jj * 2 + warpM] = cnV[t];
                sNegIc[jj * 2 + warpM] = cnI[t];
            }
        }
    }
    __syncthreads();

    if (tid < 128) {
        // row anchors -> chunk bj
        float bpV = -2.f, bnV = 3.5e38f;
        int bpI = 1 << 30, bnI = 1 << 30;
#pragma unroll
        for (int wn = 0; wn < 4; wn++) {
            selMax(bpV, bpI, sPosV[tid * 4 + wn], sPosI[tid * 4 + wn]);
            selMin(bnV, bnI, sNegV[tid * 4 + wn], sNegI[tid * 4 + wn]);
        }
        int iRow = iBase + tid;
        g_posV[bj][iRow] = bpV;
        g_posI[bj][iRow] = bpI;
        g_negV[bj][iRow] = bnV;
        g_negI[bj][iRow] = bnI;

        if (!diag) {
            // column anchors -> chunk bi
            float qpV = -2.f, qnV = 3.5e38f;
            int qpI = 1 << 30, qnI = 1 << 30;
#pragma unroll
            for (int wm = 0; wm < 2; wm++) {
                selMax(qpV, qpI, sPosVc[tid * 2 + wm], sPosIc[tid * 2 + wm]);
                selMin(qnV, qnI, sNegVc[tid * 2 + wm], sNegIc[tid * 2 + wm]);
            }
            int jRow = jBase + tid;
            g_posV[bi][jRow] = qpV;
            g_posI[bi][jRow] = qpI;
            g_negV[bi][jRow] = qnV;
            g_negI[bi][jRow] = qnI;
        }
    }
}

// ===================== kernel 3: merge chunk partials =====================
__global__ void mergeKernel(int B) {
    int i = blockIdx.x * blockDim.x + threadIdx.x;
    if (i >= B) return;
    float bv = -2.f; int bi = 1 << 30;
    float nv = 3.5e38f; int ni = 1 << 30;
    for (int c = 0; c < NCHUNK; c++) {
        selMax(bv, bi, g_posV[c][i], g_posI[c][i]);
        selMin(nv, ni, g_negV[c][i], g_negI[c][i]);
    }
    g_hardPos[i] = (bi < BMAX) ? bi : 0;
    g_hardNeg[i] = (ni < BMAX) ? ni : 0;
    g_valid[i]   = (bv > -0.5f) && (nv < 1e37f) ? 1 : 0;
}

// ===================== kernel 4: exact dp/dn recompute =====================
__global__ void lossKernel(const float* __restrict__ emb, int D) {
    int i  = blockIdx.x;
    int hp = g_hardPos[i];
    int hn = g_hardNeg[i];
    const float* a = emb + (size_t)i  * D;
    const float* p = emb + (size_t)hp * D;
    const float* n = emb + (size_t)hn * D;
    float sp = 0.f, sn = 0.f;
    for (int k = threadIdx.x * 4; k < D; k += blockDim.x * 4) {
        float4 va = *reinterpret_cast<const float4*>(a + k);
        float4 vp = *reinterpret_cast<const float4*>(p + k);
        float4 vn = *reinterpret_cast<const float4*>(n + k);
        float d;
        d = va.x - vp.x + 1e-6f; sp += d * d;
        d = va.y - vp.y + 1e-6f; sp += d * d;
        d = va.z - vp.z + 1e-6f; sp += d * d;
        d = va.w - vp.w + 1e-6f; sp += d * d;
        d = va.x - vn.x + 1e-6f; sn += d * d;
        d = va.y - vn.y + 1e-6f; sn += d * d;
        d = va.z - vn.z + 1e-6f; sn += d * d;
        d = va.w - vn.w + 1e-6f; sn += d * d;
    }
    for (int off = 16; off > 0; off >>= 1) {
        sp += __shfl_down_sync(0xFFFFFFFFu, sp, off);
        sn += __shfl_down_sync(0xFFFFFFFFu, sn, off);
    }
    __shared__ float wsp[4], wsn[4];
    int w = threadIdx.x >> 5;
    if ((threadIdx.x & 31) == 0) { wsp[w] = sp; wsn[w] = sn; }
    __syncthreads();
    if (threadIdx.x == 0) {
        float tp = wsp[0] + wsp[1] + wsp[2] + wsp[3];
        float tn = wsn[0] + wsn[1] + wsn[2] + wsn[3];
        float per = fmaxf(sqrtf(tp) - sqrtf(tn) + 0.3f, 0.f);
        g_loss[i] = g_valid[i] ? per : 0.f;
    }
}

// ===================== kernel 5: final reduction =====================
__global__ void finalKernel(float* __restrict__ out, int B) {
    __shared__ float ssum[1024];
    __shared__ int   scnt[1024];
    float s = 0.f; int c = 0;
    for (int i = threadIdx.x; i < B; i += 1024) {
        s += g_loss[i];
        c += g_valid[i];
    }
    ssum[threadIdx.x] = s;
    scnt[threadIdx.x] = c;
    __syncthreads();
    for (int off = 512; off > 0; off >>= 1) {
        if (threadIdx.x < off) {
            ssum[threadIdx.x] += ssum[threadIdx.x + off];
            scnt[threadIdx.x] += scnt[threadIdx.x + off];
        }
        __syncthreads();
    }
    if (threadIdx.x == 0)
        out[0] = (scnt[0] > 0) ? ssum[0] / (float)scnt[0] : 0.f;
}

// ===================== launch =====================
extern "C" void kernel_launch(void* const* d_in, const int* in_sizes, int n_in,
                              void* d_out, int out_size) {
    const float* emb    = (const float*)d_in[0];
    const int*   labels = (const int*)d_in[1];
    float*       out    = (float*)d_out;
    int B = in_sizes[1];
    int D = in_sizes[0] / B;

    cudaFuncSetAttribute(distKernel, cudaFuncAttributeMaxDynamicSharedMemorySize, SMEM_TOTAL);

    convKernel<<<B, 256>>>(emb, D);
    int nb = B / BM;
    int ntiles = nb * (nb + 1) / 2;
    distKernel<<<ntiles, 256, SMEM_TOTAL>>>(labels, B, D);
    mergeKernel<<<(B + 255) / 256, 256>>>(B);
    lossKernel<<<B, 128>>>(emb, D);
    finalKernel<<<1, 1024>>>(out, B);
}

// round 5
// speedup vs baseline: 14.8141x; 1.0026x over previous
#include <cuda_runtime.h>
#include <cuda_bf16.h>
#include <cstdint>
#include <math.h>

// ===================== constants =====================
#define BMAX   4096
#define DMAX   2048
#define BM 128
#define BN 128
#define TBK 64                      // bf16 K per chunk = 128 bytes/row
#define STAGES 3
#define A_BYTES (BM*TBK*2)          // 16384
#define B_BYTES (BN*TBK*2)          // 16384
#define STAGE_BYTES (A_BYTES+B_BYTES)   // 32768
#define META_OFF (STAGES*STAGE_BYTES)   // 98304 (labels/sq, 2 KB)
#define SMEM_TOTAL (META_OFF + 2048)    // 100352 -> 2 CTAs/SM guaranteed
#define NCHUNK (BMAX/BN)            // 32

// ===================== device scratch =====================
__device__ __nv_bfloat16 g_ebf[(size_t)BMAX * DMAX];
__device__ float g_sq[BMAX];
__device__ float g_posV[NCHUNK][BMAX];
__device__ int   g_posI[NCHUNK][BMAX];
__device__ float g_negV[NCHUNK][BMAX];
__device__ int   g_negI[NCHUNK][BMAX];
__device__ int   g_valid[BMAX];
__device__ float g_loss[BMAX];

// ===================== helpers =====================
__device__ __forceinline__ uint32_t smem_u32(const void* p) {
    uint32_t a;
    asm("{ .reg .u64 t; cvta.to.shared.u64 t, %1; cvt.u32.u64 %0, t; }" : "=r"(a) : "l"(p));
    return a;
}
__device__ __forceinline__ void cpa16(uint32_t s, const void* g) {
    asm volatile("cp.async.cg.shared.global [%0], [%1], 16;" :: "r"(s), "l"(g));
}
#define CPA_COMMIT() asm volatile("cp.async.commit_group;" ::: "memory")
#define CPA_WAIT(N)  asm volatile("cp.async.wait_group %0;" :: "n"(N) : "memory")

__device__ __forceinline__ void ldsm4(uint32_t* r, uint32_t addr) {
    asm volatile("ldmatrix.sync.aligned.m8n8.x4.shared.b16 {%0,%1,%2,%3}, [%4];"
                 : "=r"(r[0]), "=r"(r[1]), "=r"(r[2]), "=r"(r[3]) : "r"(addr));
}
__device__ __forceinline__ void mma16816(float* c, const uint32_t* a, const uint32_t* b) {
    asm volatile(
        "mma.sync.aligned.m16n8k16.row.col.f32.bf16.bf16.f32 "
        "{%0,%1,%2,%3}, {%4,%5,%6,%7}, {%8,%9}, {%0,%1,%2,%3};"
        : "+f"(c[0]), "+f"(c[1]), "+f"(c[2]), "+f"(c[3])
        : "r"(a[0]), "r"(a[1]), "r"(a[2]), "r"(a[3]), "r"(b[0]), "r"(b[1]));
}

__device__ __forceinline__ void selMax(float& v, int& i, float nv, int ni) {
    if (nv > v || (nv == v && ni < i)) { v = nv; i = ni; }
}
__device__ __forceinline__ void selMin(float& v, int& i, float nv, int ni) {
    if (nv < v || (nv == v && ni < i)) { v = nv; i = ni; }
}

// ===================== kernel 1: fp32 -> bf16 + row sumsq =====================
__global__ void convKernel(const float* __restrict__ emb, int D) {
    int i = blockIdx.x;
    const float4* row = reinterpret_cast<const float4*>(emb + (size_t)i * D);
    __nv_bfloat162* orow = reinterpret_cast<__nv_bfloat162*>(g_ebf + (size_t)i * D);
    float s = 0.f;
    for (int k = threadIdx.x; k < D / 4; k += blockDim.x) {
        float4 v = row[k];
        s += v.x * v.x + v.y * v.y + v.z * v.z + v.w * v.w;
        __nv_bfloat162 h0, h1;
        h0.x = __float2bfloat16(v.x); h0.y = __float2bfloat16(v.y);
        h1.x = __float2bfloat16(v.z); h1.y = __float2bfloat16(v.w);
        orow[2 * k] = h0; orow[2 * k + 1] = h1;
    }
    for (int off = 16; off > 0; off >>= 1)
        s += __shfl_down_sync(0xFFFFFFFFu, s, off);
    __shared__ float ws[8];
    if ((threadIdx.x & 31) == 0) ws[threadIdx.x >> 5] = s;
    __syncthreads();
    if (threadIdx.x == 0) {
        float t = 0.f;
        for (int w = 0; w < (int)(blockDim.x >> 5); w++) t += ws[w];
        g_sq[i] = t;
    }
}

// ===================== kernel 2: bf16 HMMA GEMM (upper triangle) + dual selection ==========
__device__ __forceinline__ void load_chunk(int tid, uint32_t sbase, int s,
                                           int iBase, int jBase, int c, int D) {
    uint32_t sA = sbase + s * STAGE_BYTES;
    uint32_t sB = sA + A_BYTES;
    int k0 = c * TBK;
    const char* gA = (const char*)(g_ebf + (size_t)iBase * D + k0);
    const char* gB = (const char*)(g_ebf + (size_t)jBase * D + k0);
#pragma unroll
    for (int t = 0; t < 4; t++) {
        int f = tid + t * 256;
        int row = f >> 3, c16 = f & 7;
        int colb = c16 * 16;
        uint32_t off = (uint32_t)(row * 128 + (colb ^ ((row & 7) << 4)));
        cpa16(sA + off, gA + (size_t)row * (size_t)(D * 2) + colb);
    }
#pragma unroll
    for (int t = 0; t < 4; t++) {
        int f = tid + t * 256;
        int row = f >> 3, c16 = f & 7;
        int colb = c16 * 16;
        uint32_t off = (uint32_t)(row * 128 + (colb ^ ((row & 7) << 4)));
        cpa16(sB + off, gB + (size_t)row * (size_t)(D * 2) + colb);
    }
    CPA_COMMIT();
}

__global__ __launch_bounds__(256, 2) void distKernel(const int* __restrict__ labels,
                                                     int B, int D) {
    extern __shared__ char sm[];
    uint32_t sbase = smem_u32(sm);

    const int tid  = threadIdx.x;
    const int wid  = tid >> 5;
    const int lane = tid & 31;
    const int warpM = wid & 1;       // 0..1 (64 rows each)
    const int warpN = wid >> 1;      // 0..3 (32 cols each)

    // decode upper-triangular tile (bi <= bj)
    const int nb = B / BM;           // 32
    int bi = 0, rem = blockIdx.x;
    while (rem >= nb - bi) { rem -= nb - bi; bi++; }
    const int bj = bi + rem;
    const int iBase = bi * BM;
    const int jBase = bj * BN;
    const bool diag = (bi == bj);

    // metadata (persistent through kernel, above stage memory)
    int*   sLabJ = (int*)  (sm + META_OFF);
    float* sSqJ  = (float*)(sm + META_OFF + 512);
    int*   sLabI = (int*)  (sm + META_OFF + 1024);
    float* sSqI  = (float*)(sm + META_OFF + 1536);
    // selection-exchange buffers: reuse stage-0 smem (only touched in epilogue)
    float* sPosV  = (float*)(sm);
    int*   sPosI  = (int*)  (sm + 2048);
    float* sNegV  = (float*)(sm + 4096);
    int*   sNegI  = (int*)  (sm + 6144);
    float* sPosVc = (float*)(sm + 8192);
    int*   sPosIc = (int*)  (sm + 9216);
    float* sNegVc = (float*)(sm + 10240);
    int*   sNegIc = (int*)  (sm + 11264);

    if (tid < 128) {
        sLabJ[tid] = labels[jBase + tid];
        sSqJ[tid]  = g_sq[jBase + tid];
        sLabI[tid] = labels[iBase + tid];
        sSqI[tid]  = g_sq[iBase + tid];
    }

    // ldmatrix per-lane invariants
    const int rowA_l = (lane & 7) + ((lane >> 3) & 1) * 8;
    const int colA_b = (lane >> 4) * 16;
    const int rowB_l = (lane & 7) + (lane >> 4) * 8;
    const int colB_b = ((lane >> 3) & 1) * 16;

    int aRow[4], bRow[2];
#pragma unroll
    for (int mf = 0; mf < 4; mf++) aRow[mf] = warpM * 64 + mf * 16 + rowA_l;
#pragma unroll
    for (int nf = 0; nf < 2; nf++) bRow[nf] = warpN * 32 + nf * 16 + rowB_l;

    float acc[4][4][4];
#pragma unroll
    for (int a = 0; a < 4; a++)
#pragma unroll
        for (int b = 0; b < 4; b++)
#pragma unroll
            for (int c = 0; c < 4; c++) acc[a][b][c] = 0.f;

    const int nch = D / TBK;     // 32

    load_chunk(tid, sbase, 0, iBase, jBase, 0, D);
    load_chunk(tid, sbase, 1, iBase, jBase, 1, D);

    for (int c = 0; c < nch; c++) {
        if (c == nch - 1) { CPA_WAIT(0); } else { CPA_WAIT(1); }
        __syncthreads();
        if (c + 2 < nch)
            load_chunk(tid, sbase, (c + 2) % STAGES, iBase, jBase, c + 2, D);

        uint32_t sA = sbase + (c % STAGES) * STAGE_BYTES;
        uint32_t sB = sA + A_BYTES;
#pragma unroll
        for (int ks = 0; ks < TBK / 16; ks++) {
            uint32_t aF[16], bF[8];
#pragma unroll
            for (int mf = 0; mf < 4; mf++) {
                int r = aRow[mf];
                uint32_t addr = sA + r * 128 + ((ks * 32 + colA_b) ^ ((r & 7) << 4));
                ldsm4(aF + mf * 4, addr);
            }
#pragma unroll
            for (int nf = 0; nf < 2; nf++) {
                int r = bRow[nf];
                uint32_t addr = sB + r * 128 + ((ks * 32 + colB_b) ^ ((r & 7) << 4));
                ldsm4(bF + nf * 4, addr);
            }
#pragma unroll
            for (int mf = 0; mf < 4; mf++)
#pragma unroll
                for (int n8 = 0; n8 < 4; n8++)
                    mma16816(acc[mf][n8], aF + mf * 4, bF + n8 * 2);
        }
    }
    __syncthreads();   // all compute done; stage smem reusable for selection exchange

    // ---- epilogue: d^2 + dual hard pos/neg selection (row + column anchors) ----
    const int g = lane >> 2;     // 0..7
    const int q = lane & 3;      // 0..3

    int   jLab[8];
    float jSq[8];
    int   jIdx[8];
#pragma unroll
    for (int n8 = 0; n8 < 4; n8++)
#pragma unroll
        for (int cc = 0; cc < 2; cc++) {
            int jj = warpN * 32 + n8 * 8 + q * 2 + cc;
            jLab[n8 * 2 + cc] = sLabJ[jj];
            jSq[n8 * 2 + cc]  = sSqJ[jj];
            jIdx[n8 * 2 + cc] = jBase + jj;
        }

    float cpV[8], cnV[8];
    int   cpI[8], cnI[8];
#pragma unroll
    for (int t = 0; t < 8; t++) {
        cpV[t] = -1.f; cpI[t] = 1 << 30;
        cnV[t] = 3.4e38f; cnI[t] = 1 << 30;
    }

#pragma unroll
    for (int mf = 0; mf < 4; mf++) {
#pragma unroll
        for (int h = 0; h < 2; h++) {
            int rl   = warpM * 64 + mf * 16 + h * 8 + g;
            int iRow = iBase + rl;
            float sqi = sSqI[rl];
            int   lab = sLabI[rl];
            float bpV = -1.f, bnV = 3.4e38f;
            int   bpI = 1 << 30, bnI = 1 << 30;
#pragma unroll
            for (int t = 0; t < 8; t++) {
                int n8 = t >> 1, cc = t & 1;
                int j = jIdx[t];
                float dot = acc[mf][n8][h * 2 + cc];
                float d2 = fmaxf(sqi + jSq[t] - 2.f * dot, 0.f);
                if (jLab[t] == lab) {
                    if (j != iRow) {
                        selMax(bpV, bpI, d2, j);
                        selMax(cpV[t], cpI[t], d2, iRow);
                    }
                } else {
                    selMin(bnV, bnI, d2, j);
                    selMin(cnV[t], cnI[t], d2, iRow);
                }
            }
#pragma unroll
            for (int off = 1; off <= 2; off <<= 1) {
                float pv = __shfl_xor_sync(0xFFFFFFFFu, bpV, off);
                int   pi = __shfl_xor_sync(0xFFFFFFFFu, bpI, off);
                selMax(bpV, bpI, pv, pi);
                float nv = __shfl_xor_sync(0xFFFFFFFFu, bnV, off);
                int   ni = __shfl_xor_sync(0xFFFFFFFFu, bnI, off);
                selMin(bnV, bnI, nv, ni);
            }
            if (q == 0) {
                sPosV[rl * 4 + warpN] = bpV;
                sPosI[rl * 4 + warpN] = bpI;
                sNegV[rl * 4 + warpN] = bnV;
                sNegI[rl * 4 + warpN] = bnI;
            }
        }
    }

    if (!diag) {
#pragma unroll
        for (int t = 0; t < 8; t++) {
#pragma unroll
            for (int off = 4; off <= 16; off <<= 1) {
                float pv = __shfl_xor_sync(0xFFFFFFFFu, cpV[t], off);
                int   pi = __shfl_xor_sync(0xFFFFFFFFu, cpI[t], off);
                selMax(cpV[t], cpI[t], pv, pi);
                float nv = __shfl_xor_sync(0xFFFFFFFFu, cnV[t], off);
                int   ni = __shfl_xor_sync(0xFFFFFFFFu, cnI[t], off);
                selMin(cnV[t], cnI[t], nv, ni);
            }
        }
        if (g == 0) {
#pragma unroll
            for (int t = 0; t < 8; t++) {
                int n8 = t >> 1, cc = t & 1;
                int jj = warpN * 32 + n8 * 8 + q * 2 + cc;
                sPosVc[jj * 2 + warpM] = cpV[t];
                sPosIc[jj * 2 + warpM] = cpI[t];
                sNegVc[jj * 2 + warpM] = cnV[t];
                sNegIc[jj * 2 + warpM] = cnI[t];
            }
        }
    }
    __syncthreads();

    if (tid < 128) {
        float bpV = -2.f, bnV = 3.5e38f;
        int bpI = 1 << 30, bnI = 1 << 30;
#pragma unroll
        for (int wn = 0; wn < 4; wn++) {
            selMax(bpV, bpI, sPosV[tid * 4 + wn], sPosI[tid * 4 + wn]);
            selMin(bnV, bnI, sNegV[tid * 4 + wn], sNegI[tid * 4 + wn]);
        }
        int iRow = iBase + tid;
        g_posV[bj][iRow] = bpV;
        g_posI[bj][iRow] = bpI;
        g_negV[bj][iRow] = bnV;
        g_negI[bj][iRow] = bnI;

        if (!diag) {
            float qpV = -2.f, qnV = 3.5e38f;
            int qpI = 1 << 30, qnI = 1 << 30;
#pragma unroll
            for (int wm = 0; wm < 2; wm++) {
                selMax(qpV, qpI, sPosVc[tid * 2 + wm], sPosIc[tid * 2 + wm]);
                selMin(qnV, qnI, sNegVc[tid * 2 + wm], sNegIc[tid * 2 + wm]);
            }
            int jRow = jBase + tid;
            g_posV[bi][jRow] = qpV;
            g_posI[bi][jRow] = qpI;
            g_negV[bi][jRow] = qnV;
            g_negI[bi][jRow] = qnI;
        }
    }
}

// ===================== kernel 3: fused merge + exact dp/dn loss =====================
__global__ __launch_bounds__(256) void lossKernel(const float* __restrict__ emb,
                                                  int D, int B) {
    int i = blockIdx.x;
    __shared__ int s_hp, s_hn, s_val;

    if (threadIdx.x < 32) {
        // NCHUNK == 32: one chunk per lane, warp-reduce (order-independent total order)
        int c = threadIdx.x;
        float pv = g_posV[c][i]; int pi = g_posI[c][i];
        float nv = g_negV[c][i]; int ni = g_negI[c][i];
#pragma unroll
        for (int off = 16; off > 0; off >>= 1) {
            float v2 = __shfl_xor_sync(0xFFFFFFFFu, pv, off);
            int   i2 = __shfl_xor_sync(0xFFFFFFFFu, pi, off);
            selMax(pv, pi, v2, i2);
            float v3 = __shfl_xor_sync(0xFFFFFFFFu, nv, off);
            int   i3 = __shfl_xor_sync(0xFFFFFFFFu, ni, off);
            selMin(nv, ni, v3, i3);
        }
        if (threadIdx.x == 0) {
            s_hp  = (pi < B) ? pi : 0;
            s_hn  = (ni < B) ? ni : 0;
            s_val = (pv > -0.5f) && (nv < 1e37f) ? 1 : 0;
        }
    }
    __syncthreads();

    int hp = s_hp, hn = s_hn;
    const float* a = emb + (size_t)i  * D;
    const float* p = emb + (size_t)hp * D;
    const float* n = emb + (size_t)hn * D;
    float sp = 0.f, sn = 0.f;
    for (int k = threadIdx.x * 4; k < D; k += blockDim.x * 4) {
        float4 va = *reinterpret_cast<const float4*>(a + k);
        float4 vp = *reinterpret_cast<const float4*>(p + k);
        float4 vn = *reinterpret_cast<const float4*>(n + k);
        float d;
        d = va.x - vp.x + 1e-6f; sp += d * d;
        d = va.y - vp.y + 1e-6f; sp += d * d;
        d = va.z - vp.z + 1e-6f; sp += d * d;
        d = va.w - vp.w + 1e-6f; sp += d * d;
        d = va.x - vn.x + 1e-6f; sn += d * d;
        d = va.y - vn.y + 1e-6f; sn += d * d;
        d = va.z - vn.z + 1e-6f; sn += d * d;
        d = va.w - vn.w + 1e-6f; sn += d * d;
    }
    for (int off = 16; off > 0; off >>= 1) {
        sp += __shfl_down_sync(0xFFFFFFFFu, sp, off);
        sn += __shfl_down_sync(0xFFFFFFFFu, sn, off);
    }
    __shared__ float wsp[8], wsn[8];
    int w = threadIdx.x >> 5;
    if ((threadIdx.x & 31) == 0) { wsp[w] = sp; wsn[w] = sn; }
    __syncthreads();
    if (threadIdx.x == 0) {
        float tp = 0.f, tn = 0.f;
#pragma unroll
        for (int ww = 0; ww < 8; ww++) { tp += wsp[ww]; tn += wsn[ww]; }
        float per = fmaxf(sqrtf(tp) - sqrtf(tn) + 0.3f, 0.f);
        g_loss[i]  = s_val ? per : 0.f;
        g_valid[i] = s_val;
    }
}

// ===================== kernel 4: final reduction =====================
__global__ void finalKernel(float* __restrict__ out, int B) {
    __shared__ float ssum[1024];
    __shared__ int   scnt[1024];
    float s = 0.f; int c = 0;
    for (int i = threadIdx.x; i < B; i += 1024) {
        s += g_loss[i];
        c += g_valid[i];
    }
    ssum[threadIdx.x] = s;
    scnt[threadIdx.x] = c;
    __syncthreads();
    for (int off = 512; off > 0; off >>= 1) {
        if (threadIdx.x < off) {
            ssum[threadIdx.x] += ssum[threadIdx.x + off];
            scnt[threadIdx.x] += scnt[threadIdx.x + off];
        }
        __syncthreads();
    }
    if (threadIdx.x == 0)
        out[0] = (scnt[0] > 0) ? ssum[0] / (float)scnt[0] : 0.f;
}

// ===================== launch =====================
extern "C" void kernel_launch(void* const* d_in, const int* in_sizes, int n_in,
                              void* d_out, int out_size) {
    const float* emb    = (const float*)d_in[0];
    const int*   labels = (const int*)d_in[1];
    float*       out    = (float*)d_out;
    int B = in_sizes[1];
    int D = in_sizes[0] / B;

    cudaFuncSetAttribute(distKernel, cudaFuncAttributeMaxDynamicSharedMemorySize, SMEM_TOTAL);

    convKernel<<<B, 256>>>(emb, D);
    int nb = B / BM;
    int ntiles = nb * (nb + 1) / 2;
    distKernel<<<ntiles, 256, SMEM_TOTAL>>>(labels, B, D);
    lossKernel<<<B, 256>>>(emb, D, B);
    finalKernel<<<1, 1024>>>(out, B);
}